// round 15
// baseline (speedup 1.0000x reference)
#include <cuda_runtime.h>
#include <cstdint>

#define L_SEQ 2048
#define DM    1024
#define NH    16
#define DV    64

// attention output scratch [4096,1024], stored pre-rounded to tf32 bits
__device__ float g_attn[2 * L_SEQ * DM];
// fc weights pre-rounded to tf32 bits
__device__ uint32_t g_wtf[DM * DM];
// V transposed per (batch,head): [n][h][dim(64)][seq(2048)] raw fp32
__device__ float g_vt[2 * NH * DV * L_SEQ];

// ---- helpers ----
__device__ __forceinline__ uint32_t s2u(const void* p) {
    uint32_t a;
    asm("{ .reg .u64 t; cvta.to.shared.u64 t, %1; cvt.u32.u64 %0, t; }"
        : "=r"(a) : "l"(p));
    return a;
}
__device__ __forceinline__ uint32_t f2tf(float f) {
    uint32_t u;
    asm("cvt.rna.tf32.f32 %0, %1;" : "=r"(u) : "f"(f));
    return u;
}
__device__ __forceinline__ float ex2(float x) {
    float r;
    asm("ex2.approx.f32 %0, %1;" : "=f"(r) : "f"(x));
    return r;
}
__device__ __forceinline__ void sts4_tf(uint32_t* p, float4 v) {
    *(uint4*)p = make_uint4(f2tf(v.x), f2tf(v.y), f2tf(v.z), f2tf(v.w));
}
__device__ __forceinline__ void mma8(float* c, const uint32_t* a,
                                     uint32_t b0, uint32_t b1) {
    asm volatile(
        "mma.sync.aligned.m16n8k8.row.col.f32.tf32.tf32.f32 "
        "{%0,%1,%2,%3}, {%4,%5,%6,%7}, {%8,%9}, {%0,%1,%2,%3};"
        : "+f"(c[0]), "+f"(c[1]), "+f"(c[2]), "+f"(c[3])
        : "r"(a[0]), "r"(a[1]), "r"(a[2]), "r"(a[3]), "r"(b0), "r"(b1));
}
__device__ __forceinline__ void ldsm4(uint32_t& r0, uint32_t& r1,
                                      uint32_t& r2, uint32_t& r3, uint32_t a) {
    asm volatile("ldmatrix.sync.aligned.m8n8.x4.shared.b16 {%0,%1,%2,%3}, [%4];"
                 : "=r"(r0), "=r"(r1), "=r"(r2), "=r"(r3) : "r"(a));
}
__device__ __forceinline__ void cpa16(uint32_t d, const void* s) {
    asm volatile("cp.async.cg.shared.global [%0], [%1], 16;" :: "r"(d), "l"(s));
}
#define CPA_COMMIT() asm volatile("cp.async.commit_group;" ::: "memory")
#define CPA_WAIT0()  asm volatile("cp.async.wait_group 0;" ::: "memory")

// exp(S/32) == 2^(S * C1);  C1 = log2(e)/32
#define C1 0.045084220027780106f

// ================= W pre-round: g_wtf = tf32(fc_w) =================
__global__ __launch_bounds__(256)
void w_prep(const float* __restrict__ W)
{
    int i = (blockIdx.x * 256 + threadIdx.x) * 4;
    float4 v = *(const float4*)(W + i);
    *(uint4*)(g_wtf + i) = make_uint4(f2tf(v.x), f2tf(v.y), f2tf(v.z), f2tf(v.w));
}

// ================= V transpose: g_vt[n][h][d][s] = V[n][s][h*64+d] ==========
__global__ __launch_bounds__(256)
void v_prep(const float* __restrict__ V)
{
    __shared__ float t[64][65];
    const int st = blockIdx.x;                // seq tile 0..31
    const int h = blockIdx.y, n = blockIdx.z;
    const int tid = threadIdx.x;

    const float* vp = V + ((size_t)(n * L_SEQ + st * 64)) * DM + h * DV;
    #pragma unroll
    for (int j = 0; j < 4; j++) {
        int idx = tid + j * 256;              // 1024 float4 slots
        int r = idx >> 4, c4 = (idx & 15) << 2;   // r=seq-local, c4=dim
        float4 v = *(const float4*)(vp + (size_t)r * DM + c4);
        t[c4 + 0][r] = v.x; t[c4 + 1][r] = v.y;
        t[c4 + 2][r] = v.z; t[c4 + 3][r] = v.w;
    }
    __syncthreads();
    float* op = g_vt + ((size_t)(n * NH + h)) * DV * L_SEQ + st * 64;
    #pragma unroll
    for (int j = 0; j < 4; j++) {
        int idx = tid + j * 256;
        int d = idx >> 4, s4 = (idx & 15) << 2;
        *(float4*)(op + (size_t)d * L_SEQ + s4) =
            make_float4(t[d][s4], t[d][s4 + 1], t[d][s4 + 2], t[d][s4 + 3]);
    }
}

// ================= attention =================
// CTA: 128 thr (4 warps) per (64-query tile, head, batch). Key blocks of 64.
// No online max; mask folded as ex2 bias. All fragments via ldmatrix.
// V consumed from g_vt (dim-major), so PV B-frags use the same ldmatrix
// pattern as the S-loop K B-frags (bit-identical data to the scalar path).
#define SD 68
#define TILE_W (64 * SD)                      // 4352 words
#define NB (L_SEQ / 64)                       // 32 key blocks
#define ATT_SMEM ((4 * TILE_W + 128) * 4)     // 70144 B -> 3 CTAs/SM

__global__ __launch_bounds__(128, 3)
void attn_mma(const float* __restrict__ Q, const float* __restrict__ K,
              const int* __restrict__ mask)
{
    extern __shared__ uint32_t sm[];
    uint32_t* sQP = sm;                       // Q tile, later reused as P tile
    const uint32_t sbase = s2u(sm);

    const int qb = blockIdx.x, hd = blockIdx.y, n = blockIdx.z;
    const int tid = threadIdx.x, w = tid >> 5, lane = tid & 31;
    const int g = lane >> 2, l4 = lane & 3;
    const int rlo = w * 16 + g, rhi = rlo + 8;

    // ldmatrix lane-address components
    const int lj  = lane & 7;
    const int mh  = (lane >> 3) & 1;
    const int mq  = (lane >> 4) & 1;

    const float* kp0 = K + ((size_t)n * L_SEQ) * DM + hd * DV;
    const float* vt0 = g_vt + ((size_t)(n * NH + hd)) * DV * L_SEQ;
    const int*   mp0 = mask + n * L_SEQ;

    uint32_t kwb = TILE_W, vwb = 2 * TILE_W, swb = 3 * TILE_W;
    const uint32_t mwb = 4 * TILE_W;

    // ---- prefetch key-block 0: K [64key x 64dim], V^T [64dim x 64key] ----
    {
        #pragma unroll
        for (int j = 0; j < 8; j++) {
            int idx = tid + j * 128;
            int r = idx >> 4, c4 = (idx & 15) << 2;
            cpa16(sbase + (uint32_t)(kwb + r * SD + c4) * 4,
                  kp0 + (size_t)r * DM + c4);
            cpa16(sbase + (uint32_t)(vwb + r * SD + c4) * 4,
                  vt0 + (size_t)r * L_SEQ + c4);
        }
        if (tid < 16) cpa16(sbase + (mwb + tid * 4) * 4, mp0 + tid * 4);
        CPA_COMMIT();
    }

    // ---- load Q tile [64 x 64] as tf32 (RNA) ----
    const float* qp = Q + ((size_t)(n * L_SEQ + qb * 64)) * DM + hd * DV;
    #pragma unroll
    for (int j = 0; j < 8; j++) {
        int idx = tid + j * 128;
        int r = idx >> 4, c4 = (idx & 15) << 2;
        sts4_tf(&sQP[r * SD + c4], *(const float4*)(qp + (size_t)r * DM + c4));
    }
    CPA_WAIT0();
    __syncthreads();

    // ---- preload Q A-fragments via ldmatrix ----
    uint32_t qa[8][4];
    #pragma unroll
    for (int kt = 0; kt < 8; kt++) {
        uint32_t a = sbase + (uint32_t)((w * 16 + mh * 8 + lj) * SD
                                        + kt * 8 + mq * 4) * 4;
        ldsm4(qa[kt][0], qa[kt][1], qa[kt][2], qa[kt][3], a);
    }
    __syncthreads();

    float oc[8][4];
    #pragma unroll
    for (int i = 0; i < 8; i++)
        #pragma unroll
        for (int j = 0; j < 4; j++) oc[i][j] = 0.f;
    float l_lo = 0.f, l_hi = 0.f;

    uint32_t* sP = sQP;

    for (int kb = 0; kb < NB; kb++) {
        const int* smk = (const int*)(sm + mwb + (kb & 1) * 64);

        // ---- prefetch K(kb+1)+mask -> spare tile ----
        if (kb + 1 < NB) {
            const float* kp = kp0 + (size_t)(kb + 1) * 64 * DM;
            #pragma unroll
            for (int j = 0; j < 8; j++) {
                int idx = tid + j * 128;
                int r = idx >> 4, c4 = (idx & 15) << 2;
                cpa16(sbase + (uint32_t)(swb + r * SD + c4) * 4,
                      kp + (size_t)r * DM + c4);
            }
            if (tid < 16)
                cpa16(sbase + (mwb + ((kb + 1) & 1) * 64 + tid * 4) * 4,
                      mp0 + (kb + 1) * 64 + tid * 4);
        }
        CPA_COMMIT();

        // ---- S = Q K^T ; K B-frags via ldmatrix ----
        float sc[8][4];
        #pragma unroll
        for (int i = 0; i < 8; i++)
            #pragma unroll
            for (int j = 0; j < 4; j++) sc[i][j] = 0.f;
        #pragma unroll
        for (int nt = 0; nt < 8; nt++) {
            uint32_t kb0[8], kb1[8];
            #pragma unroll
            for (int q = 0; q < 4; q++) {
                uint32_t a = sbase + (uint32_t)(kwb + (nt * 8 + lj) * SD
                                + (2 * q + mq) * 8 + mh * 4) * 4;
                ldsm4(kb0[2 * q], kb1[2 * q], kb0[2 * q + 1], kb1[2 * q + 1], a);
            }
            #pragma unroll
            for (int kt = 0; kt < 8; kt++)
                mma8(sc[nt], qa[kt], kb0[kt], kb1[kt]);
        }
        __syncthreads();   // all warps done reading K tile

        // ---- prefetch V^T(kb+1) -> dead K tile ----
        if (kb + 1 < NB) {
            const float* vp = vt0 + (size_t)(kb + 1) * 64;
            #pragma unroll
            for (int j = 0; j < 8; j++) {
                int idx = tid + j * 128;
                int r = idx >> 4, c4 = (idx & 15) << 2;
                cpa16(sbase + (uint32_t)(kwb + r * SD + c4) * 4,
                      vp + (size_t)r * L_SEQ + c4);
            }
        }
        CPA_COMMIT();

        // ---- p = 2^(S*C1 + bias); accumulate sums; stage P (tf32) ----
        #pragma unroll
        for (int nt = 0; nt < 8; nt++) {
            int2 mk = *(const int2*)&smk[nt * 8 + 2 * l4];
            float b0 = mk.x ? 0.f : -1e30f;
            float b1 = mk.y ? 0.f : -1e30f;
            float p0 = ex2(fmaf(sc[nt][0], C1, b0));
            float p1 = ex2(fmaf(sc[nt][1], C1, b1));
            float p2 = ex2(fmaf(sc[nt][2], C1, b0));
            float p3 = ex2(fmaf(sc[nt][3], C1, b1));
            l_lo += p0 + p1;
            l_hi += p2 + p3;
            int col = nt * 8 + 2 * l4;
            *(uint2*)&sP[rlo * SD + col] = make_uint2(f2tf(p0), f2tf(p1));
            *(uint2*)&sP[rhi * SD + col] = make_uint2(f2tf(p2), f2tf(p3));
        }
        __syncwarp();   // P rows warp-private; ldmatrix reads cross-lane

        // ---- O += P V ; P A-frags + V^T B-frags via ldmatrix ----
        uint32_t pa[8][4];
        #pragma unroll
        for (int kt = 0; kt < 8; kt++) {
            uint32_t a = sbase + (uint32_t)((w * 16 + mh * 8 + lj) * SD
                                            + kt * 8 + mq * 4) * 4;
            ldsm4(pa[kt][0], pa[kt][1], pa[kt][2], pa[kt][3], a);
        }
        #pragma unroll
        for (int nt = 0; nt < 8; nt++) {
            uint32_t vb0[8], vb1[8];
            #pragma unroll
            for (int q = 0; q < 4; q++) {
                uint32_t a = sbase + (uint32_t)(vwb + (nt * 8 + lj) * SD
                                + (2 * q + mq) * 8 + mh * 4) * 4;
                ldsm4(vb0[2 * q], vb1[2 * q], vb0[2 * q + 1], vb1[2 * q + 1], a);
            }
            #pragma unroll
            for (int kt = 0; kt < 8; kt++)
                mma8(oc[nt], pa[kt], vb0[kt], vb1[kt]);
        }

        CPA_WAIT0();
        __syncthreads();

        uint32_t oldk = kwb, oldv = vwb;
        kwb = swb; vwb = oldk; swb = oldv;
    }

    // ---- one-time row-sum reduction across the lane quad ----
    l_lo += __shfl_xor_sync(0xffffffffu, l_lo, 1);
    l_lo += __shfl_xor_sync(0xffffffffu, l_lo, 2);
    l_hi += __shfl_xor_sync(0xffffffffu, l_hi, 1);
    l_hi += __shfl_xor_sync(0xffffffffu, l_hi, 2);

    // ---- epilogue: normalize, round to tf32, store ----
    float il_lo = 1.f / l_lo, il_hi = 1.f / l_hi;
    float* olo = g_attn + ((size_t)(n * L_SEQ + qb * 64 + rlo)) * DM + hd * DV;
    float* ohi = g_attn + ((size_t)(n * L_SEQ + qb * 64 + rhi)) * DM + hd * DV;
    #pragma unroll
    for (int nt = 0; nt < 8; nt++) {
        int col = nt * 8 + 2 * l4;
        *(uint2*)(olo + col) = make_uint2(f2tf(oc[nt][0] * il_lo),
                                          f2tf(oc[nt][1] * il_lo));
        *(uint2*)(ohi + col) = make_uint2(f2tf(oc[nt][2] * il_hi),
                                          f2tf(oc[nt][3] * il_hi));
    }
}

// ================= FC: out = X W^T + b (pre-rounded, cp.async x2, ldmatrix) ==
#define FSD 36
#define FTILE_W (128 * FSD)                    // 4608 words
#define FC_SMEM (4 * FTILE_W * 4)              // 73728 B

__global__ __launch_bounds__(256, 2)
void fc_mma(const float* __restrict__ B, float* __restrict__ out)
{
    extern __shared__ uint32_t fsm[];
    const uint32_t fbase = s2u(fsm);

    const int ot = blockIdx.x, mt0 = blockIdx.y;
    const int tid = threadIdx.x, wid = tid >> 5, lane = tid & 31;
    const int wm = wid & 1, wn = wid >> 1;
    const int g = lane >> 2, l4 = lane & 3;
    const int lj = lane & 7, mh = (lane >> 3) & 1, mq = (lane >> 4) & 1;

    const float*    xb = g_attn + (size_t)(mt0 * 128) * DM;
    const uint32_t* wb = g_wtf + (size_t)(ot * 128) * DM;

    #pragma unroll
    for (int j = 0; j < 4; j++) {
        int idx = tid + j * 256;
        int r = idx >> 3, c4 = (idx & 7) << 2;
        uint32_t off = (uint32_t)(r * FSD + c4) * 4;
        cpa16(fbase + off, xb + (size_t)r * DM + c4);
        cpa16(fbase + 2 * FTILE_W * 4 + off, wb + (size_t)r * DM + c4);
    }
    CPA_COMMIT();

    float c[4][4][4];
    #pragma unroll
    for (int a = 0; a < 4; a++)
        #pragma unroll
        for (int b = 0; b < 4; b++)
            #pragma unroll
            for (int d = 0; d < 4; d++) c[a][b][d] = 0.f;

    for (int kb = 0; kb < DM / 32; kb++) {
        const int buf = kb & 1;
        const uint32_t sXw = (uint32_t)(buf * FTILE_W);
        const uint32_t sWw = (uint32_t)(2 * FTILE_W + buf * FTILE_W);

        CPA_WAIT0();
        __syncthreads();

        if (kb + 1 < DM / 32) {
            const int nb = buf ^ 1;
            #pragma unroll
            for (int j = 0; j < 4; j++) {
                int idx = tid + j * 256;
                int r = idx >> 3, c4 = (idx & 7) << 2;
                uint32_t off = (uint32_t)(nb * FTILE_W + r * FSD + c4) * 4;
                cpa16(fbase + off, xb + (size_t)r * DM + (kb + 1) * 32 + c4);
                cpa16(fbase + 2 * FTILE_W * 4 + off,
                      wb + (size_t)r * DM + (kb + 1) * 32 + c4);
            }
        }
        CPA_COMMIT();

        #pragma unroll
        for (int kt = 0; kt < 4; kt++) {
            uint32_t bfr[4][2];
            #pragma unroll
            for (int q = 0; q < 2; q++) {
                uint32_t a = fbase + (uint32_t)(sWw
                    + (wn * 32 + (2 * q + mq) * 8 + lj) * FSD
                    + kt * 8 + mh * 4) * 4;
                ldsm4(bfr[2 * q][0], bfr[2 * q][1],
                      bfr[2 * q + 1][0], bfr[2 * q + 1][1], a);
            }
            #pragma unroll
            for (int mt = 0; mt < 4; mt++) {
                uint32_t a4[4];
                uint32_t a = fbase + (uint32_t)(sXw
                    + (wm * 64 + mt * 16 + mh * 8 + lj) * FSD
                    + kt * 8 + mq * 4) * 4;
                ldsm4(a4[0], a4[1], a4[2], a4[3], a);
                #pragma unroll
                for (int nt = 0; nt < 4; nt++)
                    mma8(c[mt][nt], a4, bfr[nt][0], bfr[nt][1]);
            }
        }
    }

    const int rbase = mt0 * 128 + wm * 64;
    const int cbase = ot * 128 + wn * 32;
    #pragma unroll
    for (int mt = 0; mt < 4; mt++) {
        int rl = rbase + mt * 16 + g, rh = rl + 8;
        #pragma unroll
        for (int nt = 0; nt < 4; nt++) {
            int col = cbase + nt * 8 + 2 * l4;
            float2 bi = *(const float2*)(B + col);
            *(float2*)(out + (size_t)rl * DM + col) =
                make_float2(c[mt][nt][0] + bi.x, c[mt][nt][1] + bi.y);
            *(float2*)(out + (size_t)rh * DM + col) =
                make_float2(c[mt][nt][2] + bi.x, c[mt][nt][3] + bi.y);
        }
    }
}

extern "C" void kernel_launch(void* const* d_in, const int* in_sizes, int n_in,
                              void* d_out, int out_size)
{
    const float* q    = (const float*)d_in[0];
    const float* k    = (const float*)d_in[1];
    const float* v    = (const float*)d_in[2];
    const int*   mask = (const int*)  d_in[3];
    const float* fw   = (const float*)d_in[4];
    const float* fb   = (const float*)d_in[5];
    float* out = (float*)d_out;

    cudaFuncSetAttribute(attn_mma, cudaFuncAttributeMaxDynamicSharedMemorySize,
                         ATT_SMEM);
    cudaFuncSetAttribute(fc_mma, cudaFuncAttributeMaxDynamicSharedMemorySize,
                         FC_SMEM);

    w_prep<<<DM * DM / 1024, 256>>>(fw);

    dim3 gv(L_SEQ / 64, NH, 2);
    v_prep<<<gv, 256>>>(v);

    dim3 g1(L_SEQ / 64, NH, 2);
    attn_mma<<<g1, 128, ATT_SMEM>>>(q, k, mask);

    dim3 g2(DM / 128, (2 * L_SEQ) / 128);
    fc_mma<<<g2, 256, FC_SMEM>>>(fb, out);
}

// round 16
// speedup vs baseline: 1.3413x; 1.3413x over previous
#include <cuda_runtime.h>
#include <cstdint>

#define L_SEQ 2048
#define DM    1024
#define NH    16
#define DV    64

// attention output scratch [4096,1024], stored pre-rounded to tf32 bits
__device__ float g_attn[2 * L_SEQ * DM];
// fc weights pre-rounded to tf32 bits
__device__ uint32_t g_wtf[DM * DM];

// ---- helpers ----
__device__ __forceinline__ uint32_t s2u(const void* p) {
    uint32_t a;
    asm("{ .reg .u64 t; cvta.to.shared.u64 t, %1; cvt.u32.u64 %0, t; }"
        : "=r"(a) : "l"(p));
    return a;
}
__device__ __forceinline__ uint32_t f2tf(float f) {
    uint32_t u;
    asm("cvt.rna.tf32.f32 %0, %1;" : "=r"(u) : "f"(f));
    return u;
}
__device__ __forceinline__ float ex2(float x) {
    float r;
    asm("ex2.approx.f32 %0, %1;" : "=f"(r) : "f"(x));
    return r;
}
__device__ __forceinline__ void sts4_tf(uint32_t* p, float4 v) {
    *(uint4*)p = make_uint4(f2tf(v.x), f2tf(v.y), f2tf(v.z), f2tf(v.w));
}
__device__ __forceinline__ void mma8(float* c, const uint32_t* a,
                                     uint32_t b0, uint32_t b1) {
    asm volatile(
        "mma.sync.aligned.m16n8k8.row.col.f32.tf32.tf32.f32 "
        "{%0,%1,%2,%3}, {%4,%5,%6,%7}, {%8,%9}, {%0,%1,%2,%3};"
        : "+f"(c[0]), "+f"(c[1]), "+f"(c[2]), "+f"(c[3])
        : "r"(a[0]), "r"(a[1]), "r"(a[2]), "r"(a[3]), "r"(b0), "r"(b1));
}
__device__ __forceinline__ void ldsm4(uint32_t& r0, uint32_t& r1,
                                      uint32_t& r2, uint32_t& r3, uint32_t a) {
    asm volatile("ldmatrix.sync.aligned.m8n8.x4.shared.b16 {%0,%1,%2,%3}, [%4];"
                 : "=r"(r0), "=r"(r1), "=r"(r2), "=r"(r3) : "r"(a));
}
__device__ __forceinline__ void cpa16(uint32_t d, const void* s) {
    asm volatile("cp.async.cg.shared.global [%0], [%1], 16;" :: "r"(d), "l"(s));
}
#define CPA_COMMIT() asm volatile("cp.async.commit_group;" ::: "memory")
#define CPA_WAIT0()  asm volatile("cp.async.wait_group 0;" ::: "memory")

// exp(S/32) == 2^(S * C1);  C1 = log2(e)/32
#define C1 0.045084220027780106f

// ================= W pre-round: g_wtf = tf32(fc_w) =================
__global__ __launch_bounds__(256)
void w_prep(const float* __restrict__ W)
{
    int i = (blockIdx.x * 256 + threadIdx.x) * 4;
    float4 v = *(const float4*)(W + i);
    *(uint4*)(g_wtf + i) = make_uint4(f2tf(v.x), f2tf(v.y), f2tf(v.z), f2tf(v.w));
}

// ================= attention (R14 best version) =================
// CTA: 128 thr (4 warps) per (64-query tile, head, batch). Key blocks of 64.
// No online max; mask folded as ex2 bias. K/P/Q fragments via ldmatrix,
// V fragments scalar (keeps peak live registers under control).
#define SD 68
#define TILE_W (64 * SD)                      // 4352 words
#define NB (L_SEQ / 64)                       // 32 key blocks
#define ATT_SMEM ((4 * TILE_W + 128) * 4)     // 70144 B -> 3 CTAs/SM

__global__ __launch_bounds__(128, 3)
void attn_mma(const float* __restrict__ Q, const float* __restrict__ K,
              const float* __restrict__ V, const int* __restrict__ mask)
{
    extern __shared__ uint32_t sm[];
    uint32_t* sQP = sm;                       // Q tile, later reused as P tile
    const uint32_t sbase = s2u(sm);

    const int qb = blockIdx.x, hd = blockIdx.y, n = blockIdx.z;
    const int tid = threadIdx.x, w = tid >> 5, lane = tid & 31;
    const int g = lane >> 2, l4 = lane & 3;
    const int rlo = w * 16 + g, rhi = rlo + 8;

    const int lj  = lane & 7;
    const int mh  = (lane >> 3) & 1;
    const int mq  = (lane >> 4) & 1;

    const float* kp0 = K + ((size_t)n * L_SEQ) * DM + hd * DV;
    const float* vp0 = V + ((size_t)n * L_SEQ) * DM + hd * DV;
    const int*   mp0 = mask + n * L_SEQ;

    uint32_t kwb = TILE_W, vwb = 2 * TILE_W, swb = 3 * TILE_W;
    const uint32_t mwb = 4 * TILE_W;

    // ---- prefetch key-block 0 (K, V, mask) via cp.async (raw fp32) ----
    {
        #pragma unroll
        for (int j = 0; j < 8; j++) {
            int idx = tid + j * 128;
            int r = idx >> 4, c4 = (idx & 15) << 2;
            cpa16(sbase + (uint32_t)(kwb + r * SD + c4) * 4,
                  kp0 + (size_t)r * DM + c4);
            cpa16(sbase + (uint32_t)(vwb + r * SD + c4) * 4,
                  vp0 + (size_t)r * DM + c4);
        }
        if (tid < 16) cpa16(sbase + (mwb + tid * 4) * 4, mp0 + tid * 4);
        CPA_COMMIT();
    }

    // ---- load Q tile [64 x 64] as tf32 (RNA) ----
    const float* qp = Q + ((size_t)(n * L_SEQ + qb * 64)) * DM + hd * DV;
    #pragma unroll
    for (int j = 0; j < 8; j++) {
        int idx = tid + j * 128;
        int r = idx >> 4, c4 = (idx & 15) << 2;
        sts4_tf(&sQP[r * SD + c4], *(const float4*)(qp + (size_t)r * DM + c4));
    }
    CPA_WAIT0();
    __syncthreads();

    // ---- preload Q A-fragments via ldmatrix ----
    uint32_t qa[8][4];
    #pragma unroll
    for (int kt = 0; kt < 8; kt++) {
        uint32_t a = sbase + (uint32_t)((w * 16 + mh * 8 + lj) * SD
                                        + kt * 8 + mq * 4) * 4;
        ldsm4(qa[kt][0], qa[kt][1], qa[kt][2], qa[kt][3], a);
    }
    __syncthreads();

    float oc[8][4];
    #pragma unroll
    for (int i = 0; i < 8; i++)
        #pragma unroll
        for (int j = 0; j < 4; j++) oc[i][j] = 0.f;
    float l_lo = 0.f, l_hi = 0.f;

    uint32_t* sP = sQP;

    for (int kb = 0; kb < NB; kb++) {
        const int* smk = (const int*)(sm + mwb + (kb & 1) * 64);

        // ---- prefetch K(kb+1)+mask -> spare tile ----
        if (kb + 1 < NB) {
            const float* kp = kp0 + (size_t)(kb + 1) * 64 * DM;
            #pragma unroll
            for (int j = 0; j < 8; j++) {
                int idx = tid + j * 128;
                int r = idx >> 4, c4 = (idx & 15) << 2;
                cpa16(sbase + (uint32_t)(swb + r * SD + c4) * 4,
                      kp + (size_t)r * DM + c4);
            }
            if (tid < 16)
                cpa16(sbase + (mwb + ((kb + 1) & 1) * 64 + tid * 4) * 4,
                      mp0 + (kb + 1) * 64 + tid * 4);
        }
        CPA_COMMIT();

        // ---- S = Q K^T ; K B-frags via ldmatrix ----
        float sc[8][4];
        #pragma unroll
        for (int i = 0; i < 8; i++)
            #pragma unroll
            for (int j = 0; j < 4; j++) sc[i][j] = 0.f;
        #pragma unroll
        for (int nt = 0; nt < 8; nt++) {
            uint32_t kb0[8], kb1[8];
            #pragma unroll
            for (int q = 0; q < 4; q++) {
                uint32_t a = sbase + (uint32_t)(kwb + (nt * 8 + lj) * SD
                                + (2 * q + mq) * 8 + mh * 4) * 4;
                ldsm4(kb0[2 * q], kb1[2 * q], kb0[2 * q + 1], kb1[2 * q + 1], a);
            }
            #pragma unroll
            for (int kt = 0; kt < 8; kt++)
                mma8(sc[nt], qa[kt], kb0[kt], kb1[kt]);
        }
        __syncthreads();   // all warps done reading K tile

        // ---- prefetch V(kb+1) -> dead K tile ----
        if (kb + 1 < NB) {
            const float* vp = vp0 + (size_t)(kb + 1) * 64 * DM;
            #pragma unroll
            for (int j = 0; j < 8; j++) {
                int idx = tid + j * 128;
                int r = idx >> 4, c4 = (idx & 15) << 2;
                cpa16(sbase + (uint32_t)(kwb + r * SD + c4) * 4,
                      vp + (size_t)r * DM + c4);
            }
        }
        CPA_COMMIT();

        // ---- p = 2^(S*C1 + bias); accumulate sums; stage P (tf32) ----
        #pragma unroll
        for (int nt = 0; nt < 8; nt++) {
            int2 mk = *(const int2*)&smk[nt * 8 + 2 * l4];
            float b0 = mk.x ? 0.f : -1e30f;
            float b1 = mk.y ? 0.f : -1e30f;
            float p0 = ex2(fmaf(sc[nt][0], C1, b0));
            float p1 = ex2(fmaf(sc[nt][1], C1, b1));
            float p2 = ex2(fmaf(sc[nt][2], C1, b0));
            float p3 = ex2(fmaf(sc[nt][3], C1, b1));
            l_lo += p0 + p1;
            l_hi += p2 + p3;
            int col = nt * 8 + 2 * l4;
            *(uint2*)&sP[rlo * SD + col] = make_uint2(f2tf(p0), f2tf(p1));
            *(uint2*)&sP[rhi * SD + col] = make_uint2(f2tf(p2), f2tf(p3));
        }
        __syncwarp();   // P rows warp-private; ldmatrix reads cross-lane

        // ---- O += P V ; P A-frags via ldmatrix, V scalar ----
        #pragma unroll
        for (int kt = 0; kt < 8; kt++) {
            uint32_t pa[4];
            uint32_t a = sbase + (uint32_t)((w * 16 + mh * 8 + lj) * SD
                                            + kt * 8 + mq * 4) * 4;
            ldsm4(pa[0], pa[1], pa[2], pa[3], a);
            #pragma unroll
            for (int nt = 0; nt < 8; nt++) {
                uint32_t b0 = sm[vwb + (kt * 8 + l4) * SD + nt * 8 + g];
                uint32_t b1 = sm[vwb + (kt * 8 + 4 + l4) * SD + nt * 8 + g];
                mma8(oc[nt], pa, b0, b1);
            }
        }

        CPA_WAIT0();
        __syncthreads();

        uint32_t oldk = kwb, oldv = vwb;
        kwb = swb; vwb = oldk; swb = oldv;
    }

    // ---- one-time row-sum reduction across the lane quad ----
    l_lo += __shfl_xor_sync(0xffffffffu, l_lo, 1);
    l_lo += __shfl_xor_sync(0xffffffffu, l_lo, 2);
    l_hi += __shfl_xor_sync(0xffffffffu, l_hi, 1);
    l_hi += __shfl_xor_sync(0xffffffffu, l_hi, 2);

    // ---- epilogue: normalize, round to tf32, store ----
    float il_lo = 1.f / l_lo, il_hi = 1.f / l_hi;
    float* olo = g_attn + ((size_t)(n * L_SEQ + qb * 64 + rlo)) * DM + hd * DV;
    float* ohi = g_attn + ((size_t)(n * L_SEQ + qb * 64 + rhi)) * DM + hd * DV;
    #pragma unroll
    for (int nt = 0; nt < 8; nt++) {
        int col = nt * 8 + 2 * l4;
        *(uint2*)(olo + col) = make_uint2(f2tf(oc[nt][0] * il_lo),
                                          f2tf(oc[nt][1] * il_lo));
        *(uint2*)(ohi + col) = make_uint2(f2tf(oc[nt][2] * il_hi),
                                          f2tf(oc[nt][3] * il_hi));
    }
}

// ======= FC: out = X W^T + b — 128x64 tiles for occupancy (512 CTAs) ========
// 8 warps as 4m x 2n; warp tile 32x32 (mt 2 x nt 4); k-chunk 32, cp.async x2.
#define FSD 36
#define FXT (128 * FSD)                        // X tile words (4608)
#define FWT (64 * FSD)                         // W tile words (2304)
#define FC_SMEM ((2 * FXT + 2 * FWT) * 4)      // 55296 B

__global__ __launch_bounds__(256, 3)
void fc_mma(const float* __restrict__ B, float* __restrict__ out)
{
    extern __shared__ uint32_t fsm[];
    const uint32_t fbase = s2u(fsm);

    const int ot = blockIdx.x, mt0 = blockIdx.y;
    const int tid = threadIdx.x, wid = tid >> 5, lane = tid & 31;
    const int wm = wid & 3, wn = wid >> 2;     // 4 m-groups x 2 n-groups
    const int g = lane >> 2, l4 = lane & 3;
    const int lj = lane & 7, mh = (lane >> 3) & 1, mq = (lane >> 4) & 1;

    const float*    xb = g_attn + (size_t)(mt0 * 128) * DM;
    const uint32_t* wb = g_wtf + (size_t)(ot * 64) * DM;

    // prefetch k-chunk 0:  X 128x32 (1024 float4), W 64x32 (512 float4)
    #pragma unroll
    for (int j = 0; j < 4; j++) {
        int idx = tid + j * 256;
        int r = idx >> 3, c4 = (idx & 7) << 2;
        cpa16(fbase + (uint32_t)(r * FSD + c4) * 4, xb + (size_t)r * DM + c4);
    }
    #pragma unroll
    for (int j = 0; j < 2; j++) {
        int idx = tid + j * 256;
        int r = idx >> 3, c4 = (idx & 7) << 2;
        cpa16(fbase + (uint32_t)(2 * FXT + r * FSD + c4) * 4,
              wb + (size_t)r * DM + c4);
    }
    CPA_COMMIT();

    float c[2][4][4];
    #pragma unroll
    for (int a = 0; a < 2; a++)
        #pragma unroll
        for (int b = 0; b < 4; b++)
            #pragma unroll
            for (int d = 0; d < 4; d++) c[a][b][d] = 0.f;

    for (int kb = 0; kb < DM / 32; kb++) {
        const int buf = kb & 1;
        const uint32_t sXw = (uint32_t)(buf * FXT);
        const uint32_t sWw = (uint32_t)(2 * FXT + buf * FWT);

        CPA_WAIT0();
        __syncthreads();

        if (kb + 1 < DM / 32) {
            const int nb = buf ^ 1;
            #pragma unroll
            for (int j = 0; j < 4; j++) {
                int idx = tid + j * 256;
                int r = idx >> 3, c4 = (idx & 7) << 2;
                cpa16(fbase + (uint32_t)(nb * FXT + r * FSD + c4) * 4,
                      xb + (size_t)r * DM + (kb + 1) * 32 + c4);
            }
            #pragma unroll
            for (int j = 0; j < 2; j++) {
                int idx = tid + j * 256;
                int r = idx >> 3, c4 = (idx & 7) << 2;
                cpa16(fbase + (uint32_t)(2 * FXT + nb * FWT + r * FSD + c4) * 4,
                      wb + (size_t)r * DM + (kb + 1) * 32 + c4);
            }
        }
        CPA_COMMIT();

        #pragma unroll
        for (int kt = 0; kt < 4; kt++) {
            // W B-fragments for nt=0..3 (rows wn*32..wn*32+31): 2 ldsm4
            uint32_t bfr[4][2];
            #pragma unroll
            for (int q = 0; q < 2; q++) {
                uint32_t a = fbase + (uint32_t)(sWw
                    + (wn * 32 + (2 * q + mq) * 8 + lj) * FSD
                    + kt * 8 + mh * 4) * 4;
                ldsm4(bfr[2 * q][0], bfr[2 * q][1],
                      bfr[2 * q + 1][0], bfr[2 * q + 1][1], a);
            }
            // X A-fragments: mt=0..1 over rows wm*32..wm*32+31
            #pragma unroll
            for (int mt = 0; mt < 2; mt++) {
                uint32_t a4[4];
                uint32_t a = fbase + (uint32_t)(sXw
                    + (wm * 32 + mt * 16 + mh * 8 + lj) * FSD
                    + kt * 8 + mq * 4) * 4;
                ldsm4(a4[0], a4[1], a4[2], a4[3], a);
                #pragma unroll
                for (int nt = 0; nt < 4; nt++)
                    mma8(c[mt][nt], a4, bfr[nt][0], bfr[nt][1]);
            }
        }
    }

    const int rbase = mt0 * 128 + wm * 32;
    const int cbase = ot * 64 + wn * 32;
    #pragma unroll
    for (int mt = 0; mt < 2; mt++) {
        int rl = rbase + mt * 16 + g, rh = rl + 8;
        #pragma unroll
        for (int nt = 0; nt < 4; nt++) {
            int col = cbase + nt * 8 + 2 * l4;
            float2 bi = *(const float2*)(B + col);
            *(float2*)(out + (size_t)rl * DM + col) =
                make_float2(c[mt][nt][0] + bi.x, c[mt][nt][1] + bi.y);
            *(float2*)(out + (size_t)rh * DM + col) =
                make_float2(c[mt][nt][2] + bi.x, c[mt][nt][3] + bi.y);
        }
    }
}

extern "C" void kernel_launch(void* const* d_in, const int* in_sizes, int n_in,
                              void* d_out, int out_size)
{
    const float* q    = (const float*)d_in[0];
    const float* k    = (const float*)d_in[1];
    const float* v    = (const float*)d_in[2];
    const int*   mask = (const int*)  d_in[3];
    const float* fw   = (const float*)d_in[4];
    const float* fb   = (const float*)d_in[5];
    float* out = (float*)d_out;

    cudaFuncSetAttribute(attn_mma, cudaFuncAttributeMaxDynamicSharedMemorySize,
                         ATT_SMEM);
    cudaFuncSetAttribute(fc_mma, cudaFuncAttributeMaxDynamicSharedMemorySize,
                         FC_SMEM);

    w_prep<<<DM * DM / 1024, 256>>>(fw);

    dim3 g1(L_SEQ / 64, NH, 2);
    attn_mma<<<g1, 128, ATT_SMEM>>>(q, k, v, mask);

    dim3 g2(DM / 64, (2 * L_SEQ) / 128);
    fc_mma<<<g2, 256, FC_SMEM>>>(fb, out);
}

// round 17
// speedup vs baseline: 1.3712x; 1.0223x over previous
#include <cuda_runtime.h>
#include <cstdint>

#define L_SEQ 2048
#define DM    1024
#define NH    16
#define DV    64

// attention output scratch [4096,1024], stored pre-rounded to tf32 bits
__device__ float g_attn[2 * L_SEQ * DM];

// ---- helpers ----
__device__ __forceinline__ uint32_t s2u(const void* p) {
    uint32_t a;
    asm("{ .reg .u64 t; cvta.to.shared.u64 t, %1; cvt.u32.u64 %0, t; }"
        : "=r"(a) : "l"(p));
    return a;
}
__device__ __forceinline__ uint32_t f2tf(float f) {
    uint32_t u;
    asm("cvt.rna.tf32.f32 %0, %1;" : "=r"(u) : "f"(f));
    return u;
}
__device__ __forceinline__ float ex2(float x) {
    float r;
    asm("ex2.approx.f32 %0, %1;" : "=f"(r) : "f"(x));
    return r;
}
__device__ __forceinline__ void sts4_tf(uint32_t* p, float4 v) {
    *(uint4*)p = make_uint4(f2tf(v.x), f2tf(v.y), f2tf(v.z), f2tf(v.w));
}
__device__ __forceinline__ void mma8(float* c, const uint32_t* a,
                                     uint32_t b0, uint32_t b1) {
    asm volatile(
        "mma.sync.aligned.m16n8k8.row.col.f32.tf32.tf32.f32 "
        "{%0,%1,%2,%3}, {%4,%5,%6,%7}, {%8,%9}, {%0,%1,%2,%3};"
        : "+f"(c[0]), "+f"(c[1]), "+f"(c[2]), "+f"(c[3])
        : "r"(a[0]), "r"(a[1]), "r"(a[2]), "r"(a[3]), "r"(b0), "r"(b1));
}
__device__ __forceinline__ void ldsm4(uint32_t& r0, uint32_t& r1,
                                      uint32_t& r2, uint32_t& r3, uint32_t a) {
    asm volatile("ldmatrix.sync.aligned.m8n8.x4.shared.b16 {%0,%1,%2,%3}, [%4];"
                 : "=r"(r0), "=r"(r1), "=r"(r2), "=r"(r3) : "r"(a));
}
__device__ __forceinline__ void cpa16(uint32_t d, const void* s) {
    asm volatile("cp.async.cg.shared.global [%0], [%1], 16;" :: "r"(d), "l"(s));
}
#define CPA_COMMIT() asm volatile("cp.async.commit_group;" ::: "memory")
#define CPA_WAIT0()  asm volatile("cp.async.wait_group 0;" ::: "memory")

// exp(S/32) == 2^(S * C1);  C1 = log2(e)/32
#define C1 0.045084220027780106f

// ================= attention (R14 best version, unchanged) =================
// CTA: 128 thr (4 warps) per (64-query tile, head, batch). Key blocks of 64.
// No online max; mask folded as ex2 bias. K/P/Q fragments via ldmatrix,
// V fragments scalar (keeps peak live registers under control).
#define SD 68
#define TILE_W (64 * SD)                      // 4352 words
#define NB (L_SEQ / 64)                       // 32 key blocks
#define ATT_SMEM ((4 * TILE_W + 128) * 4)     // 70144 B -> 3 CTAs/SM

__global__ __launch_bounds__(128, 3)
void attn_mma(const float* __restrict__ Q, const float* __restrict__ K,
              const float* __restrict__ V, const int* __restrict__ mask)
{
    extern __shared__ uint32_t sm[];
    uint32_t* sQP = sm;                       // Q tile, later reused as P tile
    const uint32_t sbase = s2u(sm);

    const int qb = blockIdx.x, hd = blockIdx.y, n = blockIdx.z;
    const int tid = threadIdx.x, w = tid >> 5, lane = tid & 31;
    const int g = lane >> 2, l4 = lane & 3;
    const int rlo = w * 16 + g, rhi = rlo + 8;

    const int lj  = lane & 7;
    const int mh  = (lane >> 3) & 1;
    const int mq  = (lane >> 4) & 1;

    const float* kp0 = K + ((size_t)n * L_SEQ) * DM + hd * DV;
    const float* vp0 = V + ((size_t)n * L_SEQ) * DM + hd * DV;
    const int*   mp0 = mask + n * L_SEQ;

    uint32_t kwb = TILE_W, vwb = 2 * TILE_W, swb = 3 * TILE_W;
    const uint32_t mwb = 4 * TILE_W;

    // ---- prefetch key-block 0 (K, V, mask) via cp.async (raw fp32) ----
    {
        #pragma unroll
        for (int j = 0; j < 8; j++) {
            int idx = tid + j * 128;
            int r = idx >> 4, c4 = (idx & 15) << 2;
            cpa16(sbase + (uint32_t)(kwb + r * SD + c4) * 4,
                  kp0 + (size_t)r * DM + c4);
            cpa16(sbase + (uint32_t)(vwb + r * SD + c4) * 4,
                  vp0 + (size_t)r * DM + c4);
        }
        if (tid < 16) cpa16(sbase + (mwb + tid * 4) * 4, mp0 + tid * 4);
        CPA_COMMIT();
    }

    // ---- load Q tile [64 x 64] as tf32 (RNA) ----
    const float* qp = Q + ((size_t)(n * L_SEQ + qb * 64)) * DM + hd * DV;
    #pragma unroll
    for (int j = 0; j < 8; j++) {
        int idx = tid + j * 128;
        int r = idx >> 4, c4 = (idx & 15) << 2;
        sts4_tf(&sQP[r * SD + c4], *(const float4*)(qp + (size_t)r * DM + c4));
    }
    CPA_WAIT0();
    __syncthreads();

    // ---- preload Q A-fragments via ldmatrix ----
    uint32_t qa[8][4];
    #pragma unroll
    for (int kt = 0; kt < 8; kt++) {
        uint32_t a = sbase + (uint32_t)((w * 16 + mh * 8 + lj) * SD
                                        + kt * 8 + mq * 4) * 4;
        ldsm4(qa[kt][0], qa[kt][1], qa[kt][2], qa[kt][3], a);
    }
    __syncthreads();

    float oc[8][4];
    #pragma unroll
    for (int i = 0; i < 8; i++)
        #pragma unroll
        for (int j = 0; j < 4; j++) oc[i][j] = 0.f;
    float l_lo = 0.f, l_hi = 0.f;

    uint32_t* sP = sQP;

    for (int kb = 0; kb < NB; kb++) {
        const int* smk = (const int*)(sm + mwb + (kb & 1) * 64);

        // ---- prefetch K(kb+1)+mask -> spare tile ----
        if (kb + 1 < NB) {
            const float* kp = kp0 + (size_t)(kb + 1) * 64 * DM;
            #pragma unroll
            for (int j = 0; j < 8; j++) {
                int idx = tid + j * 128;
                int r = idx >> 4, c4 = (idx & 15) << 2;
                cpa16(sbase + (uint32_t)(swb + r * SD + c4) * 4,
                      kp + (size_t)r * DM + c4);
            }
            if (tid < 16)
                cpa16(sbase + (mwb + ((kb + 1) & 1) * 64 + tid * 4) * 4,
                      mp0 + (kb + 1) * 64 + tid * 4);
        }
        CPA_COMMIT();

        // ---- S = Q K^T ; K B-frags via ldmatrix ----
        float sc[8][4];
        #pragma unroll
        for (int i = 0; i < 8; i++)
            #pragma unroll
            for (int j = 0; j < 4; j++) sc[i][j] = 0.f;
        #pragma unroll
        for (int nt = 0; nt < 8; nt++) {
            uint32_t kb0[8], kb1[8];
            #pragma unroll
            for (int q = 0; q < 4; q++) {
                uint32_t a = sbase + (uint32_t)(kwb + (nt * 8 + lj) * SD
                                + (2 * q + mq) * 8 + mh * 4) * 4;
                ldsm4(kb0[2 * q], kb1[2 * q], kb0[2 * q + 1], kb1[2 * q + 1], a);
            }
            #pragma unroll
            for (int kt = 0; kt < 8; kt++)
                mma8(sc[nt], qa[kt], kb0[kt], kb1[kt]);
        }
        __syncthreads();   // all warps done reading K tile

        // ---- prefetch V(kb+1) -> dead K tile ----
        if (kb + 1 < NB) {
            const float* vp = vp0 + (size_t)(kb + 1) * 64 * DM;
            #pragma unroll
            for (int j = 0; j < 8; j++) {
                int idx = tid + j * 128;
                int r = idx >> 4, c4 = (idx & 15) << 2;
                cpa16(sbase + (uint32_t)(kwb + r * SD + c4) * 4,
                      vp + (size_t)r * DM + c4);
            }
        }
        CPA_COMMIT();

        // ---- p = 2^(S*C1 + bias); accumulate sums; stage P (tf32) ----
        #pragma unroll
        for (int nt = 0; nt < 8; nt++) {
            int2 mk = *(const int2*)&smk[nt * 8 + 2 * l4];
            float b0 = mk.x ? 0.f : -1e30f;
            float b1 = mk.y ? 0.f : -1e30f;
            float p0 = ex2(fmaf(sc[nt][0], C1, b0));
            float p1 = ex2(fmaf(sc[nt][1], C1, b1));
            float p2 = ex2(fmaf(sc[nt][2], C1, b0));
            float p3 = ex2(fmaf(sc[nt][3], C1, b1));
            l_lo += p0 + p1;
            l_hi += p2 + p3;
            int col = nt * 8 + 2 * l4;
            *(uint2*)&sP[rlo * SD + col] = make_uint2(f2tf(p0), f2tf(p1));
            *(uint2*)&sP[rhi * SD + col] = make_uint2(f2tf(p2), f2tf(p3));
        }
        __syncwarp();   // P rows warp-private; ldmatrix reads cross-lane

        // ---- O += P V ; P A-frags via ldmatrix, V scalar ----
        #pragma unroll
        for (int kt = 0; kt < 8; kt++) {
            uint32_t pa[4];
            uint32_t a = sbase + (uint32_t)((w * 16 + mh * 8 + lj) * SD
                                            + kt * 8 + mq * 4) * 4;
            ldsm4(pa[0], pa[1], pa[2], pa[3], a);
            #pragma unroll
            for (int nt = 0; nt < 8; nt++) {
                uint32_t b0 = sm[vwb + (kt * 8 + l4) * SD + nt * 8 + g];
                uint32_t b1 = sm[vwb + (kt * 8 + 4 + l4) * SD + nt * 8 + g];
                mma8(oc[nt], pa, b0, b1);
            }
        }

        CPA_WAIT0();
        __syncthreads();

        uint32_t oldk = kwb, oldv = vwb;
        kwb = swb; vwb = oldk; swb = oldv;
    }

    // ---- one-time row-sum reduction across the lane quad ----
    l_lo += __shfl_xor_sync(0xffffffffu, l_lo, 1);
    l_lo += __shfl_xor_sync(0xffffffffu, l_lo, 2);
    l_hi += __shfl_xor_sync(0xffffffffu, l_hi, 1);
    l_hi += __shfl_xor_sync(0xffffffffu, l_hi, 2);

    // ---- epilogue: normalize, round to tf32, store ----
    float il_lo = 1.f / l_lo, il_hi = 1.f / l_hi;
    float* olo = g_attn + ((size_t)(n * L_SEQ + qb * 64 + rlo)) * DM + hd * DV;
    float* ohi = g_attn + ((size_t)(n * L_SEQ + qb * 64 + rhi)) * DM + hd * DV;
    #pragma unroll
    for (int nt = 0; nt < 8; nt++) {
        int col = nt * 8 + 2 * l4;
        *(uint2*)(olo + col) = make_uint2(f2tf(oc[nt][0] * il_lo),
                                          f2tf(oc[nt][1] * il_lo));
        *(uint2*)(ohi + col) = make_uint2(f2tf(oc[nt][2] * il_hi),
                                          f2tf(oc[nt][3] * il_hi));
    }
}

// ==== FC: out = X W^T + b (R14 shape; W read RAW fp32, HW-truncated) ========
// CTA 128x128 tile, 256 thr (8 warps, 2m x 4n), k-chunk 32, cp.async x2.
// X comes from g_attn (already tf32-rounded); W raw bits go straight into
// the MMA (tensor core truncates to tf32 — same mechanism as attn's K/V).
#define FSD 36
#define FTILE_W (128 * FSD)                    // 4608 words
#define FC_SMEM (4 * FTILE_W * 4)              // 73728 B

__global__ __launch_bounds__(256, 2)
void fc_mma(const float* __restrict__ W, const float* __restrict__ B,
            float* __restrict__ out)
{
    extern __shared__ uint32_t fsm[];
    const uint32_t fbase = s2u(fsm);

    const int ot = blockIdx.x, mt0 = blockIdx.y;
    const int tid = threadIdx.x, wid = tid >> 5, lane = tid & 31;
    const int wm = wid & 1, wn = wid >> 1;
    const int g = lane >> 2, l4 = lane & 3;
    const int lj = lane & 7, mh = (lane >> 3) & 1, mq = (lane >> 4) & 1;

    const float* xb = g_attn + (size_t)(mt0 * 128) * DM;
    const float* wb = W + (size_t)(ot * 128) * DM;

    #pragma unroll
    for (int j = 0; j < 4; j++) {
        int idx = tid + j * 256;
        int r = idx >> 3, c4 = (idx & 7) << 2;
        uint32_t off = (uint32_t)(r * FSD + c4) * 4;
        cpa16(fbase + off, xb + (size_t)r * DM + c4);
        cpa16(fbase + 2 * FTILE_W * 4 + off, wb + (size_t)r * DM + c4);
    }
    CPA_COMMIT();

    float c[4][4][4];
    #pragma unroll
    for (int a = 0; a < 4; a++)
        #pragma unroll
        for (int b = 0; b < 4; b++)
            #pragma unroll
            for (int d = 0; d < 4; d++) c[a][b][d] = 0.f;

    for (int kb = 0; kb < DM / 32; kb++) {
        const int buf = kb & 1;
        const uint32_t sXw = (uint32_t)(buf * FTILE_W);
        const uint32_t sWw = (uint32_t)(2 * FTILE_W + buf * FTILE_W);

        CPA_WAIT0();
        __syncthreads();

        if (kb + 1 < DM / 32) {
            const int nb = buf ^ 1;
            #pragma unroll
            for (int j = 0; j < 4; j++) {
                int idx = tid + j * 256;
                int r = idx >> 3, c4 = (idx & 7) << 2;
                uint32_t off = (uint32_t)(nb * FTILE_W + r * FSD + c4) * 4;
                cpa16(fbase + off, xb + (size_t)r * DM + (kb + 1) * 32 + c4);
                cpa16(fbase + 2 * FTILE_W * 4 + off,
                      wb + (size_t)r * DM + (kb + 1) * 32 + c4);
            }
        }
        CPA_COMMIT();

        #pragma unroll
        for (int kt = 0; kt < 4; kt++) {
            uint32_t bfr[4][2];
            #pragma unroll
            for (int q = 0; q < 2; q++) {
                uint32_t a = fbase + (uint32_t)(sWw
                    + (wn * 32 + (2 * q + mq) * 8 + lj) * FSD
                    + kt * 8 + mh * 4) * 4;
                ldsm4(bfr[2 * q][0], bfr[2 * q][1],
                      bfr[2 * q + 1][0], bfr[2 * q + 1][1], a);
            }
            #pragma unroll
            for (int mt = 0; mt < 4; mt++) {
                uint32_t a4[4];
                uint32_t a = fbase + (uint32_t)(sXw
                    + (wm * 64 + mt * 16 + mh * 8 + lj) * FSD
                    + kt * 8 + mq * 4) * 4;
                ldsm4(a4[0], a4[1], a4[2], a4[3], a);
                #pragma unroll
                for (int nt = 0; nt < 4; nt++)
                    mma8(c[mt][nt], a4, bfr[nt][0], bfr[nt][1]);
            }
        }
    }

    const int rbase = mt0 * 128 + wm * 64;
    const int cbase = ot * 128 + wn * 32;
    #pragma unroll
    for (int mt = 0; mt < 4; mt++) {
        int rl = rbase + mt * 16 + g, rh = rl + 8;
        #pragma unroll
        for (int nt = 0; nt < 4; nt++) {
            int col = cbase + nt * 8 + 2 * l4;
            float2 bi = *(const float2*)(B + col);
            *(float2*)(out + (size_t)rl * DM + col) =
                make_float2(c[mt][nt][0] + bi.x, c[mt][nt][1] + bi.y);
            *(float2*)(out + (size_t)rh * DM + col) =
                make_float2(c[mt][nt][2] + bi.x, c[mt][nt][3] + bi.y);
        }
    }
}

extern "C" void kernel_launch(void* const* d_in, const int* in_sizes, int n_in,
                              void* d_out, int out_size)
{
    const float* q    = (const float*)d_in[0];
    const float* k    = (const float*)d_in[1];
    const float* v    = (const float*)d_in[2];
    const int*   mask = (const int*)  d_in[3];
    const float* fw   = (const float*)d_in[4];
    const float* fb   = (const float*)d_in[5];
    float* out = (float*)d_out;

    cudaFuncSetAttribute(attn_mma, cudaFuncAttributeMaxDynamicSharedMemorySize,
                         ATT_SMEM);
    cudaFuncSetAttribute(fc_mma, cudaFuncAttributeMaxDynamicSharedMemorySize,
                         FC_SMEM);

    dim3 g1(L_SEQ / 64, NH, 2);
    attn_mma<<<g1, 128, ATT_SMEM>>>(q, k, v, mask);

    dim3 g2(DM / 128, (2 * L_SEQ) / 128);
    fc_mma<<<g2, 256, FC_SMEM>>>(fw, fb, out);
}